// round 16
// baseline (speedup 1.0000x reference)
#include <cuda_runtime.h>
#include <math.h>

#define NBATCH 8
#define NPTS   8192
#define NCAND  2048
#define NQ     4
#define NCQ    (NCAND / NQ)          // 512 candidates per quarter
#define NG4Q   (NCQ / 4)             // 128 groups of 4
#define NG8Q   (NCQ / 8)             // 64 groups of 8
#define NTHREADS 512
#define PPT    4
#define PTS_PER_BLOCK (NTHREADS * PPT)  // 2048
#define PGRP   (NPTS / PTS_PER_BLOCK)   // 4 point-groups per batch

#define BASE_ALPHA 0.05f
#define EPS_F      1e-6f

typedef unsigned long long ull;

// Scratch (allocation-free rule: __device__ globals; zero-init is benign:
// ikey arrays use inverted keys (0 == +inf identity for atomicMax) and replays
// recompute identical values; counters are reset by their last finisher).
__device__ ull      g_ikey1[(size_t)NBATCH * NPTS];
__device__ ull      g_ikey2[(size_t)NBATCH * NPTS];
__device__ float    g_ref1[(size_t)NBATCH * NPTS * 3];
__device__ float    g_rmax1[NBATCH * PGRP];
__device__ float    g_rmax2[NBATCH * PGRP];
__device__ unsigned g_c1[NBATCH * PGRP];
__device__ unsigned g_c2[NBATCH * PGRP];

// ---- packed fp32x2 helpers (sm_100+; ptxas never emits these from C++) ----
__device__ __forceinline__ ull ffma2(ull a, ull b, ull c) {
    ull d;
    asm("fma.rn.f32x2 %0, %1, %2, %3;" : "=l"(d) : "l"(a), "l"(b), "l"(c));
    return d;
}
__device__ __forceinline__ ull fmul2(ull a, ull b) {
    ull d;
    asm("mul.rn.f32x2 %0, %1, %2;" : "=l"(d) : "l"(a), "l"(b));
    return d;
}
__device__ __forceinline__ ull pack2(float lo, float hi) {
    ull r;
    asm("mov.b64 %0, {%1, %2};" : "=l"(r) : "f"(lo), "f"(hi));
    return r;
}
__device__ __forceinline__ void unpack2(ull v, float& lo, float& hi) {
    asm("mov.b64 {%0, %1}, %2;" : "=f"(lo), "=f"(hi) : "l"(v));
}

// Ordered key: flipped float score (monotonic as unsigned) || candidate index.
// min(okey) == min score; ties -> smaller global index (jnp.argmin semantics).
// Stored INVERTED (ikey = ~okey) so atomicMax with zero-init state works.
__device__ __forceinline__ ull make_ikey(float s, int idx) {
    unsigned int b = __float_as_uint(s);
    b = (b & 0x80000000u) ? ~b : (b | 0x80000000u);
    return ~(((ull)b << 32) | (unsigned int)idx);
}
__device__ __forceinline__ float ikey_score(ull ik) {
    unsigned int fb = (unsigned int)((~ik) >> 32);
    unsigned int b = (fb & 0x80000000u) ? (fb ^ 0x80000000u) : ~fb;
    return __uint_as_float(b);
}
__device__ __forceinline__ int ikey_idx(ull ik) {
    return (int)((~ik) & 0xffffffffu);
}

__device__ __forceinline__ float max4(const float* __restrict__ a) {
    float m = a[0];
#pragma unroll
    for (int i = 1; i < PGRP; i++) m = fmaxf(m, a[i]);
    return m;
}

// d = sqrt(max(s + |p|^2, 0)) where s = -2 p.c + |c|^2  (true min distance).
__device__ __forceinline__ float dist_from_ikey(ull ik, float rx, float ry, float rz) {
    const float p2 = fmaf(rx, rx, fmaf(ry, ry, rz * rz));
    return sqrtf(fmaxf(ikey_score(ik) + p2, 0.0f));
}

// First j in [0,8) of the winning group-of-8 with score <= best. The scalar
// chain (incl. h recompute) is bitwise-identical to the packed lanes.
__device__ __forceinline__ int resolve8(const float* __restrict__ xs,
                                        const float* __restrict__ ys,
                                        const float* __restrict__ zs,
                                        float ax, float ay, float az, float best) {
    int r = 7;
#pragma unroll
    for (int j = 6; j >= 0; j--) {
        const float x = xs[j], y = ys[j], z = zs[j];
        const float h = fmaf(x, x, fmaf(y, y, z * z));
        const float s = fmaf(ax, x, fmaf(ay, y, fmaf(az, z, h)));
        if (s <= best) r = j;
    }
    return r;
}

// ITER==1: points = pred, keys -> g_ikey1, partial maxes -> g_rmax1.
// ITER==2: points = refined1 (computed in prologue, quarter 0 stores g_ref1),
//          keys -> g_ikey2, partial maxes -> g_rmax2.
template <int ITER>
__global__ __launch_bounds__(NTHREADS, 1)
void scan_kernel(const float* __restrict__ pred,
                 const float* __restrict__ partial) {
    __shared__ float4 sX[NG4Q], sY[NG4Q], sZ[NG4Q];   // 6 KB, SoA-by-4, no H
    __shared__ float s_wmax[NTHREADS / 32];
    __shared__ int s_last;

    const int quarter = blockIdx.x >> 2;
    const int pgrp    = blockIdx.x & (PGRP - 1);
    const int b       = blockIdx.y;

    const float* __restrict__ ppb = partial + (size_t)b * NCAND * 3;
    const float4* __restrict__ pp4 = (const float4*)(ppb + (size_t)quarter * NCQ * 3);

    // Transpose load: 3 float4 AoS -> X,Y,Z float4 per group-of-4.
    for (int g = threadIdx.x; g < NG4Q; g += NTHREADS) {
        float4 A = pp4[3 * g + 0];   // x0 y0 z0 x1
        float4 B = pp4[3 * g + 1];   // y1 z1 x2 y2
        float4 C = pp4[3 * g + 2];   // z2 x3 y3 z3
        sX[g] = make_float4(A.x, A.w, B.z, C.y);
        sY[g] = make_float4(A.y, B.x, B.w, C.z);
        sZ[g] = make_float4(A.z, B.y, C.x, C.w);
    }
    __syncthreads();

    int   pidx[PPT];
    float rx[PPT], ry[PPT], rz[PPT];
#pragma unroll
    for (int k = 0; k < PPT; k++)
        pidx[k] = pgrp * PTS_PER_BLOCK + k * NTHREADS + threadIdx.x;

    if (ITER == 1) {
#pragma unroll
        for (int k = 0; k < PPT; k++) {
            const float* pb = pred + ((size_t)b * NPTS + pidx[k]) * 3;
            rx[k] = pb[0]; ry[k] = pb[1]; rz[k] = pb[2];
        }
    } else {
        // Compute refined1 = update1(pred) from merged iter-1 keys.
        const float rbm1 = 1.0f / (max4(g_rmax1 + b * PGRP) + EPS_F);
#pragma unroll
        for (int k = 0; k < PPT; k++) {
            const size_t base = (size_t)b * NPTS + pidx[k];
            const float* pb = pred + base * 3;
            float x = pb[0], y = pb[1], z = pb[2];
            const ull ik = g_ikey1[base];
            const float d = dist_from_ikey(ik, x, y, z);
            const float a = BASE_ALPHA * (2.0f - d * rbm1);
            const float* pc = ppb + 3 * ikey_idx(ik);
            x += a * (pc[0] - x);
            y += a * (pc[1] - y);
            z += a * (pc[2] - z);
            rx[k] = x; ry[k] = y; rz[k] = z;
            if (quarter == 0) {            // one copy is enough (values identical)
                float* po = g_ref1 + base * 3;
                po[0] = x; po[1] = y; po[2] = z;
            }
        }
    }

    // Packed broadcast coefficients: a = -2p  (score = a.c + |c|^2).
    ull ax[PPT], ay[PPT], az[PPT];
    float best[PPT];
    int gbest[PPT];
#pragma unroll
    for (int k = 0; k < PPT; k++) {
        ax[k] = pack2(-2.0f * rx[k], -2.0f * rx[k]);
        ay[k] = pack2(-2.0f * ry[k], -2.0f * ry[k]);
        az[k] = pack2(-2.0f * rz[k], -2.0f * rz[k]);
        best[k] = 3.0e38f;
        gbest[k] = 0;
    }

    const ulonglong2* __restrict__ uX = (const ulonglong2*)sX;
    const ulonglong2* __restrict__ uY = (const ulonglong2*)sY;
    const ulonglong2* __restrict__ uZ = (const ulonglong2*)sZ;

    for (int g = 0; g < NG8Q; g++) {
        // 6 LDS.128 per group-of-8 candidates
        ulonglong2 Xa = uX[2 * g], Xb = uX[2 * g + 1];
        ulonglong2 Ya = uY[2 * g], Yb = uY[2 * g + 1];
        ulonglong2 Za = uZ[2 * g], Zb = uZ[2 * g + 1];

        // h = x*x + (y*y + z*z), packed, shared across all PPT points
        ull hal = ffma2(Xa.x, Xa.x, ffma2(Ya.x, Ya.x, fmul2(Za.x, Za.x)));
        ull hah = ffma2(Xa.y, Xa.y, ffma2(Ya.y, Ya.y, fmul2(Za.y, Za.y)));
        ull hbl = ffma2(Xb.x, Xb.x, ffma2(Yb.x, Yb.x, fmul2(Zb.x, Zb.x)));
        ull hbh = ffma2(Xb.y, Xb.y, ffma2(Yb.y, Yb.y, fmul2(Zb.y, Zb.y)));

#pragma unroll
        for (int k = 0; k < PPT; k++) {
            ull t0 = ffma2(ax[k], Xa.x, ffma2(ay[k], Ya.x, ffma2(az[k], Za.x, hal)));
            ull t1 = ffma2(ax[k], Xa.y, ffma2(ay[k], Ya.y, ffma2(az[k], Za.y, hah)));
            ull t2 = ffma2(ax[k], Xb.x, ffma2(ay[k], Yb.x, ffma2(az[k], Zb.x, hbl)));
            ull t3 = ffma2(ax[k], Xb.y, ffma2(ay[k], Yb.y, ffma2(az[k], Zb.y, hbh)));
            float s0, s1, s2, s3, s4, s5, s6, s7;
            unpack2(t0, s0, s1);
            unpack2(t1, s2, s3);
            unpack2(t2, s4, s5);
            unpack2(t3, s6, s7);
            float m = fminf(fminf(fminf(s0, s1), fminf(s2, s3)),
                            fminf(fminf(s4, s5), fminf(s6, s7)));
            if (m < best[k]) { best[k] = m; gbest[k] = g; }  // strict <: first wins
        }
    }

    // Publish inverted keys via atomicMax (merged min across quarters).
    ull* __restrict__ ikey = (ITER == 1) ? g_ikey1 : g_ikey2;
    const float* fX = (const float*)sX;
    const float* fY = (const float*)sY;
    const float* fZ = (const float*)sZ;
#pragma unroll
    for (int k = 0; k < PPT; k++) {
        const int gq = 8 * gbest[k];
        const int ci = quarter * NCQ + gq +
                       resolve8(fX + gq, fY + gq, fZ + gq,
                                -2.0f * rx[k], -2.0f * ry[k], -2.0f * rz[k], best[k]);
        atomicMax(&ikey[(size_t)b * NPTS + pidx[k]], make_ikey(best[k], ci));
    }
    __threadfence();   // release key writes before counter increment

    // Last finisher of this (b, pgrp) group computes the merged block max.
    unsigned* __restrict__ cnt  = ((ITER == 1) ? g_c1 : g_c2) + b * PGRP + pgrp;
    float*    __restrict__ rmax = ((ITER == 1) ? g_rmax1 : g_rmax2) + b * PGRP + pgrp;
    if (threadIdx.x == 0) {
        unsigned t = atomicAdd(cnt, 1u);
        s_last = (t == NQ - 1);
        if (t == NQ - 1) *cnt = 0u;     // reset for the next graph replay
    }
    __syncthreads();
    if (s_last) {
        __threadfence();                 // acquire the other quarters' key writes
        float mx = 0.0f;
#pragma unroll
        for (int k = 0; k < PPT; k++) {
            const ull ik = ikey[(size_t)b * NPTS + pidx[k]];
            mx = fmaxf(mx, dist_from_ikey(ik, rx[k], ry[k], rz[k]));
        }
#pragma unroll
        for (int off = 16; off > 0; off >>= 1)
            mx = fmaxf(mx, __shfl_xor_sync(0xffffffffu, mx, off));
        if ((threadIdx.x & 31) == 0) s_wmax[threadIdx.x >> 5] = mx;
        __syncthreads();
        if (threadIdx.x == 0) {
            float mm = s_wmax[0];
#pragma unroll
            for (int w = 1; w < NTHREADS / 32; w++) mm = fmaxf(mm, s_wmax[w]);
            *rmax = mm;
        }
    }
}

// refined1 (stored) -> apply update 2 -> out.  1 pt/thread, coalesced.
__global__ __launch_bounds__(256)
void finalize_kernel(const float* __restrict__ partial,
                     float* __restrict__ out) {
    const int i = blockIdx.x * 256 + threadIdx.x;   // global point index
    if (i >= NBATCH * NPTS) return;
    const int b = i / NPTS;
    const float* __restrict__ ppb = partial + (size_t)b * NCAND * 3;

    float rx = g_ref1[3 * i], ry = g_ref1[3 * i + 1], rz = g_ref1[3 * i + 2];

    const float rbm2 = 1.0f / (max4(g_rmax2 + b * PGRP) + EPS_F);
    const ull ik = g_ikey2[i];
    const float d = dist_from_ikey(ik, rx, ry, rz);
    const float a = BASE_ALPHA * (2.0f - d * rbm2);
    const float* pc = ppb + 3 * ikey_idx(ik);
    rx += a * (pc[0] - rx);
    ry += a * (pc[1] - ry);
    rz += a * (pc[2] - rz);

    out[3 * i + 0] = rx;
    out[3 * i + 1] = ry;
    out[3 * i + 2] = rz;
}

extern "C" void kernel_launch(void* const* d_in, const int* in_sizes, int n_in,
                              void* d_out, int out_size) {
    const float* pred    = (const float*)d_in[0];   // [8,8192,3]
    const float* partial = (const float*)d_in[1];   // [8,2048,3]
    float* out = (float*)d_out;                     // [8,8192,3]

    const dim3 sgrid(NQ * PGRP, NBATCH);            // 128 blocks, 1/SM, 16 warps
    const int  fgrid = (NBATCH * NPTS + 255) / 256; // 256

    scan_kernel<1><<<sgrid, NTHREADS>>>(pred, partial);
    scan_kernel<2><<<sgrid, NTHREADS>>>(pred, partial);
    finalize_kernel<<<fgrid, 256>>>(partial, out);
}